// round 5
// baseline (speedup 1.0000x reference)
#include <cuda_runtime.h>
#include <math.h>

#define BB 256
#define IND 512
#define OUTD 512
#define ED 256
#define DELTA_C 0.1f
#define LN_EPS_C 1e-5f

typedef unsigned long long u64;

// Scratch (device globals — no allocation allowed)
__device__ float g_Wt[IND * OUTD];         // Wt[i][o] = W[o][i]
__device__ float g_scores[IND * OUTD];     // scores[i][o]
__device__ float4 g_WM[IND * (OUTD / 2)];  // (w_lo, w_hi, m_lo, m_hi) per (i, o-pair)

// ---- packed f32x2 helpers (sm_100+; only add/mul/fma exist packed) ----
__device__ __forceinline__ u64 pack2(float lo, float hi) {
    u64 r; asm("mov.b64 %0, {%1,%2};" : "=l"(r) : "f"(lo), "f"(hi)); return r;
}
#define FMA2(d,a,b,c) asm("fma.rn.f32x2 %0,%1,%2,%3;" : "=l"(d) : "l"(a),"l"(b),"l"(c))
#define MUL2(d,a,b)   asm("mul.rn.f32x2 %0,%1,%2;"    : "=l"(d) : "l"(a),"l"(b))
#define UNPACK2(lo,hi,v) asm("mov.b64 {%0,%1}, %2;" : "=f"(lo),"=f"(hi) : "l"(v))

// ============================================================
// Kernel 1 (fused prep): blocks [0,256): transpose W -> g_Wt
//                        blocks [256,384): scores GEMM
// ============================================================
__global__ __launch_bounds__(128) void kernel_prep(
    const float* __restrict__ W, const float* __restrict__ PE,
    const float* __restrict__ AW, const float* __restrict__ AB) {
    __shared__ float tile[32][33];
    __shared__ float pe[32][18];
    const int blk = blockIdx.x;
    const int tid = threadIdx.x;

    if (blk < 256) {
        // ---- transpose tile ----
        int tx = tid & 31, ty = tid >> 5;  // 4 row-groups
        int c = (blk & 15) * 32 + tx;
        int r0 = (blk >> 4) * 32;
#pragma unroll
        for (int j = 0; j < 32; j += 4)
            tile[ty + j][tx] = W[(r0 + ty + j) * IND + c];
        __syncthreads();
        int c2 = (blk >> 4) * 32 + tx;
        int r2 = (blk & 15) * 32;
#pragma unroll
        for (int j = 0; j < 32; j += 4)
            g_Wt[(r2 + ty + j) * OUTD + c2] = tile[tx][ty + j];
    } else {
        // ---- scores: scores[i][o] = AB[o] + sum_e PE[i][e]*AW[o][e] ----
        const int bs = blk - 256;
        const int o = (bs & 3) * 128 + tid;
        const int i0 = (bs >> 2) * 16;

        u64 acc[8];
        const u64 z = pack2(0.f, 0.f);
#pragma unroll
        for (int j = 0; j < 8; j++) acc[j] = z;

        const float* awrow = AW + o * ED;

        for (int e0 = 0; e0 < ED; e0 += 32) {
            __syncthreads();
#pragma unroll
            for (int idx = tid; idx < 512; idx += 128) {
                int ii = idx >> 5, e = idx & 31;
                pe[e][ii] = PE[(i0 + ii) * ED + e0 + e];
            }
            __syncthreads();
#pragma unroll
            for (int e4 = 0; e4 < 32; e4 += 4) {
                float4 w4 = *(const float4*)(awrow + e0 + e4);
                float we[4] = {w4.x, w4.y, w4.z, w4.w};
#pragma unroll
                for (int k = 0; k < 4; k++) {
                    u64 ww = pack2(we[k], we[k]);
#pragma unroll
                    for (int j = 0; j < 8; j++) {
                        u64 p = *(const u64*)&pe[e4 + k][2 * j];
                        FMA2(acc[j], p, ww, acc[j]);
                    }
                }
            }
        }
        float bo = AB[o];
#pragma unroll
        for (int j = 0; j < 8; j++) {
            float lo, hi; UNPACK2(lo, hi, acc[j]);
            g_scores[(i0 + 2 * j) * OUTD + o] = lo + bo;
            g_scores[(i0 + 2 * j + 1) * OUTD + o] = hi + bo;
        }
    }
}

// ============================================================
// Kernel 2: LayerNorm -> sigmoid -> write interleaved g_WM float4
// ============================================================
__global__ __launch_bounds__(128) void kernel_ln(
    const float* __restrict__ LG, const float* __restrict__ LB) {
    const int tid = threadIdx.x;
    const int i0 = blockIdx.x * 4;
    const int w = tid >> 5, lane = tid & 31;
    __shared__ float mus[4], rss[4];

    {
        const float* row = g_scores + (i0 + w) * OUTD;
        float s = 0.f, s2 = 0.f;
#pragma unroll
        for (int k = 0; k < 16; k++) {
            float v = row[lane + 32 * k];
            s += v; s2 += v * v;
        }
#pragma unroll
        for (int off = 16; off > 0; off >>= 1) {
            s  += __shfl_xor_sync(0xffffffffu, s,  off);
            s2 += __shfl_xor_sync(0xffffffffu, s2, off);
        }
        if (lane == 0) {
            float mu = s * (1.f / OUTD);
            float var = s2 * (1.f / OUTD) - mu * mu;
            mus[w] = mu;
            rss[w] = rsqrtf(var + LN_EPS_C);
        }
    }
    __syncthreads();
#pragma unroll
    for (int ii = 0; ii < 4; ii++) {
        float mu = mus[ii], rs = rss[ii];
        const int i = i0 + ii;
#pragma unroll
        for (int j = 0; j < 2; j++) {
            int p = tid + j * 128;  // o-pair index [0,256)
            float2 s2v = *(const float2*)(g_scores + i * OUTD + 2 * p);
            float2 w2v = *(const float2*)(g_Wt + i * OUTD + 2 * p);
            float glo = LG[2 * p],     blo = LB[2 * p];
            float ghi = LG[2 * p + 1], bhi = LB[2 * p + 1];
            float vlo = (s2v.x - mu) * rs * glo + blo;
            float vhi = (s2v.y - mu) * rs * ghi + bhi;
            float siglo = 1.f / (1.f + __expf(-vlo));
            float sighi = 1.f / (1.f + __expf(-vhi));
            float4 q;
            q.x = w2v.x; q.y = w2v.y;
            q.z = fabsf(w2v.x) * siglo;
            q.w = fabsf(w2v.y) * sighi;
            g_WM[i * (OUTD / 2) + p] = q;
        }
    }
}

// ============================================================
// Kernel 3 (main): out[b,o] = x@Wt + 0.1*(max_i t*M - sum_i t*M)
//
// grid (8 o-tiles of 64, 64 b-tiles of 4), block 256, 3 blocks/SM.
// Thread: to = tid&15 -> o-pairs {bx*32+to, bx*32+to+16}; si = tid>>4
// -> i-chunk of 32. Register tile 4b x 2 o-pairs, packed f32x2 for
// fma/mul; max done scalar on the ALU pipe (no packed max in PTX).
// LDG.128 double-buffered in 2-i groups. Cross-si smem reduction.
// ============================================================
#define MAIN_SMEM (4 * IND * 16)  // 32 KB

__global__ __launch_bounds__(256, 3) void kernel_main(
    const float* __restrict__ X, float* __restrict__ out) {
    extern __shared__ char smem_raw[];
    ulonglong2 (*xt)[IND] = (ulonglong2 (*)[IND])smem_raw;  // [4][512]
    float* red = (float*)smem_raw;

    const int tid = threadIdx.x;
    const int to = tid & 15;
    const int si = tid >> 4;        // [0,16), i-chunk of 32
    const int b0 = blockIdx.y * 4;

    // Stage x and t = x*|x| duplicated for f32x2 broadcast.
    for (int idx = tid; idx < 4 * IND; idx += 256) {
        int b = idx >> 9, i = idx & 511;
        float xv = X[(b0 + b) * IND + i];
        float tv = xv * fabsf(xv);
        xt[b][i] = make_ulonglong2(pack2(xv, xv), pack2(tv, tv));
    }
    __syncthreads();

    u64 c[4][2];
    float mxl[4][2], mxh[4][2];
    const u64 z = pack2(0.f, 0.f);
    const u64 n01 = pack2(-DELTA_C, -DELTA_C);
#pragma unroll
    for (int b = 0; b < 4; b++) {
        c[b][0] = z; c[b][1] = z;
        mxl[b][0] = -INFINITY; mxl[b][1] = -INFINITY;
        mxh[b][0] = -INFINITY; mxh[b][1] = -INFINITY;
    }

    const int ib = si * 32;
    const float4* __restrict__ base = g_WM + blockIdx.x * 32 + to;

    // load 2-i group (2 o-pairs each) at row i
    auto LD = [&](float4 q[2][2], int i) {
        q[0][0] = __ldg(base + i * (OUTD / 2));
        q[0][1] = __ldg(base + i * (OUTD / 2) + 16);
        q[1][0] = __ldg(base + (i + 1) * (OUTD / 2));
        q[1][1] = __ldg(base + (i + 1) * (OUTD / 2) + 16);
    };
    // compute 2-i group starting at row i
    auto COMP = [&](float4 q[2][2], int i) {
#pragma unroll
        for (int k = 0; k < 2; k++) {
            u64 w2a = pack2(q[k][0].x, q[k][0].y);
            u64 m2a = pack2(q[k][0].z, q[k][0].w);
            u64 w2b = pack2(q[k][1].x, q[k][1].y);
            u64 m2b = pack2(q[k][1].z, q[k][1].w);
#pragma unroll
            for (int b = 0; b < 4; b++) {
                ulonglong2 v = xt[b][i + k];
                FMA2(c[b][0], v.x, w2a, c[b][0]);
                u64 pa; MUL2(pa, v.y, m2a);
                FMA2(c[b][0], pa, n01, c[b][0]);
                float palo, pahi; UNPACK2(palo, pahi, pa);
                mxl[b][0] = fmaxf(mxl[b][0], palo);
                mxh[b][0] = fmaxf(mxh[b][0], pahi);
                FMA2(c[b][1], v.x, w2b, c[b][1]);
                u64 pb; MUL2(pb, v.y, m2b);
                FMA2(c[b][1], pb, n01, c[b][1]);
                float pblo, pbhi; UNPACK2(pblo, pbhi, pb);
                mxl[b][1] = fmaxf(mxl[b][1], pblo);
                mxh[b][1] = fmaxf(mxh[b][1], pbhi);
            }
        }
    };

    float4 qc[2][2], qn[2][2];
    LD(qc, ib);
#pragma unroll 1
    for (int g = 0; g < 8; g++) {
        LD(qn, ib + 4 * g + 2);
        COMP(qc, ib + 4 * g);
        if (g < 7) LD(qc, ib + 4 * g + 4);
        COMP(qn, ib + 4 * g + 2);
    }

    __syncthreads();  // xt done; reuse as reduction buffer (32 KB exactly)

    // red planes: kind k in {c_lo, c_hi, mx_lo, mx_hi} x [b][j][si][to]
#define RIDX(k, b, j, s, t) ((((((k) * 4 + (b)) * 2 + (j)) * 16 + (s)) * 16) + (t))
#pragma unroll
    for (int b = 0; b < 4; b++) {
#pragma unroll
        for (int j = 0; j < 2; j++) {
            float clo, chi;
            UNPACK2(clo, chi, c[b][j]);
            red[RIDX(0, b, j, si, to)] = clo;
            red[RIDX(1, b, j, si, to)] = chi;
            red[RIDX(2, b, j, si, to)] = mxl[b][j];
            red[RIDX(3, b, j, si, to)] = mxh[b][j];
        }
    }
    __syncthreads();

    // Final combine: 128 threads; thread -> (b2, pair) writes float2.
    if (tid < 128) {
        const int b2 = tid >> 5;
        const int pl = tid & 31;        // j2*16 + to2
        const int j2 = pl >> 4;
        const int to2 = pl & 15;
        float slo = 0.f, shi = 0.f, Mlo = -INFINITY, Mhi = -INFINITY;
#pragma unroll
        for (int s = 0; s < 16; s++) {
            slo += red[RIDX(0, b2, j2, s, to2)];
            shi += red[RIDX(1, b2, j2, s, to2)];
            Mlo = fmaxf(Mlo, red[RIDX(2, b2, j2, s, to2)]);
            Mhi = fmaxf(Mhi, red[RIDX(3, b2, j2, s, to2)]);
        }
        float2 r;
        r.x = slo + DELTA_C * Mlo;
        r.y = shi + DELTA_C * Mhi;
        *(float2*)(out + (b0 + b2) * OUTD + blockIdx.x * 64 + pl * 2) = r;
    }
#undef RIDX
}

// ============================================================
extern "C" void kernel_launch(void* const* d_in, const int* in_sizes, int n_in,
                              void* d_out, int out_size) {
    const float* x  = (const float*)d_in[0];
    const float* w  = (const float*)d_in[1];
    const float* pe = (const float*)d_in[2];
    const float* aw = (const float*)d_in[3];
    const float* ab = (const float*)d_in[4];
    const float* lg = (const float*)d_in[5];
    const float* lb = (const float*)d_in[6];
    float* out = (float*)d_out;

    kernel_prep<<<384, 128>>>(w, pe, aw, ab);
    kernel_ln<<<128, 128>>>(lg, lb);
    kernel_main<<<dim3(8, 64), 256, MAIN_SMEM>>>(x, out);
}